// round 8
// baseline (speedup 1.0000x reference)
#include <cuda_runtime.h>
#include <cuda_fp16.h>
#include <cstdint>

// ---------------- problem dims ----------------
constexpr int B_   = 32;
constexpr int CIN  = 256;
constexpr int COUT = 256;
constexpr int HW   = 1024;   // 32x32
constexpr int TDIM = 256;
constexpr int HID  = 64;
constexpr int E_   = 4;
constexpr int TAPS = 9;

// ---------------- device scratch (static: allocation rules) ----------------
__device__ __align__(16) __half g_xh[(size_t)B_ * CIN * HW];              // x in fp16
__device__ float  g_pooled[B_ * CIN];
__device__ float  g_rw[B_ * E_];
__device__ __align__(16) __half g_weff[(size_t)B_ * TAPS * COUT * CIN];   // [b][tap][cout][cin]

// ---------------- helpers ----------------
#define SW128(off)  ((off) ^ (((off) >> 3) & 0x70))   // 128B-row swizzle

__device__ __forceinline__ uint32_t smem_u32(const void* p) {
    uint32_t a;
    asm("{ .reg .u64 t; cvta.to.shared.u64 t, %1; cvt.u32.u64 %0, t; }"
        : "=r"(a) : "l"(p));
    return a;
}
__device__ __forceinline__ void ldsm_x4(uint32_t* r, uint32_t addr) {
    asm volatile("ldmatrix.sync.aligned.m8n8.x4.shared.b16 {%0,%1,%2,%3}, [%4];"
                 : "=r"(r[0]), "=r"(r[1]), "=r"(r[2]), "=r"(r[3]) : "r"(addr));
}
__device__ __forceinline__ void mma16816(float* c, const uint32_t* a,
                                         uint32_t b0, uint32_t b1) {
    asm volatile(
        "mma.sync.aligned.m16n8k16.row.col.f32.f16.f16.f32 "
        "{%0,%1,%2,%3}, {%4,%5,%6,%7}, {%8,%9}, {%0,%1,%2,%3};"
        : "+f"(c[0]), "+f"(c[1]), "+f"(c[2]), "+f"(c[3])
        : "r"(a[0]), "r"(a[1]), "r"(a[2]), "r"(a[3]), "r"(b0), "r"(b1));
}
__device__ __forceinline__ void cp_async16(uint32_t dst, const void* src) {
    asm volatile("cp.async.cg.shared.global [%0], [%1], 16;" :: "r"(dst), "l"(src));
}
#define CP_COMMIT() asm volatile("cp.async.commit_group;" ::: "memory")
#define CP_WAIT(N)  asm volatile("cp.async.wait_group %0;" :: "n"(N) : "memory")

// ---------------- kernel 1: pool (mean over HW) + fp32->fp16 convert ----------------
__global__ __launch_bounds__(256) void pool_convert_kernel(const float* __restrict__ x) {
    int wid = threadIdx.x >> 5, lid = threadIdx.x & 31;
    int rc = blockIdx.x * 8 + wid;               // 0 .. B_*CIN-1
    const float4* xp = reinterpret_cast<const float4*>(x + (size_t)rc * HW);
    uint2* op = reinterpret_cast<uint2*>(g_xh + (size_t)rc * HW);
    float s = 0.f;
    #pragma unroll
    for (int i = 0; i < 8; i++) {
        float4 v = xp[lid + i * 32];
        s += (v.x + v.y) + (v.z + v.w);
        __half2 h0 = __floats2half2_rn(v.x, v.y);
        __half2 h1 = __floats2half2_rn(v.z, v.w);
        uint2 u;
        u.x = *reinterpret_cast<uint32_t*>(&h0);
        u.y = *reinterpret_cast<uint32_t*>(&h1);
        op[lid + i * 32] = u;
    }
    #pragma unroll
    for (int o = 16; o > 0; o >>= 1) s += __shfl_xor_sync(0xFFFFFFFFu, s, o);
    if (lid == 0) g_pooled[rc] = s * (1.f / 1024.f);
}

// ---------------- kernel 2: router MLP + softmax -> g_rw ----------------
__global__ __launch_bounds__(HID) void router_kernel(
    const float* __restrict__ te,
    const float* __restrict__ Wq, const float* __restrict__ bq,
    const float* __restrict__ Wk, const float* __restrict__ bk,
    const float* __restrict__ Wv, const float* __restrict__ bv,
    const float* __restrict__ Wm1, const float* __restrict__ bm1,
    const float* __restrict__ Wm2, const float* __restrict__ bm2,
    const float* __restrict__ Wc, const float* __restrict__ bc) {
    int b = blockIdx.x, j = threadIdx.x;
    __shared__ float s_in[TDIM], s_p[CIN], s_xa[HID], s_h[HID], s_xm[HID], s_l[E_];
    for (int i = j; i < TDIM; i += HID) s_in[i] = te[b * TDIM + i];
    for (int i = j; i < CIN; i += HID) s_p[i] = g_pooled[b * CIN + i];
    __syncthreads();

    float q = bq[j], k = bk[j], v = bv[j];
    for (int i = 0; i < TDIM; i++) q += Wq[j * TDIM + i] * s_in[i];
    for (int i = 0; i < CIN; i++) {
        float p = s_p[i];
        k += Wk[j * CIN + i] * p;
        v += Wv[j * CIN + i] * p;
    }
    float attn = 1.f / (1.f + expf(-(q * k)));
    float xa = v * attn;
    s_xa[j] = xa;
    __syncthreads();

    float h = bm1[j];
    for (int i = 0; i < HID; i++) h += Wm1[j * HID + i] * s_xa[i];
    h = h / (1.f + expf(-h));         // silu
    s_h[j] = h;
    __syncthreads();

    float xm = xa + bm2[j];
    for (int i = 0; i < HID; i++) xm += Wm2[j * HID + i] * s_h[i];
    s_xm[j] = xm;
    __syncthreads();

    if (j < E_) {
        float l = bc[j];
        for (int i = 0; i < HID; i++) l += Wc[j * HID + i] * s_xm[i];
        s_l[j] = l;
    }
    __syncthreads();
    if (j == 0) {
        float mx = s_l[0];
        for (int e = 1; e < E_; e++) mx = fmaxf(mx, s_l[e]);
        float sm = 0.f, ex[E_];
        for (int e = 0; e < E_; e++) { ex[e] = expf(s_l[e] - mx); sm += ex[e]; }
        float inv = 1.f / sm;
        for (int e = 0; e < E_; e++) g_rw[b * E_ + e] = ex[e] * inv;
    }
}

// ---------------- kernel 3: mix expert weights -> g_weff [b][tap][cout][cin] fp16 ----------------
__global__ __launch_bounds__(256) void mix_kernel(const float* __restrict__ weight) {
    int o = blockIdx.x, c = threadIdx.x;
    __shared__ float ws[E_ * CIN * TAPS];   // 36 KB: weight[:, o, :, :]
    __shared__ float srw[B_ * E_];
    for (int e = 0; e < E_; e++) {
        const float* src = weight + (size_t)(e * COUT + o) * (CIN * TAPS);
        for (int i = c; i < CIN * TAPS; i += 256) ws[e * CIN * TAPS + i] = src[i];
    }
    for (int i = c; i < B_ * E_; i += 256) srw[i] = g_rw[i];
    __syncthreads();

    float wv[E_][TAPS];
    #pragma unroll
    for (int e = 0; e < E_; e++)
        #pragma unroll
        for (int t = 0; t < TAPS; t++) wv[e][t] = ws[e * CIN * TAPS + c * TAPS + t];

    for (int b = 0; b < B_; b++) {
        float r0 = srw[b * 4 + 0], r1 = srw[b * 4 + 1];
        float r2 = srw[b * 4 + 2], r3 = srw[b * 4 + 3];
        #pragma unroll
        for (int t = 0; t < TAPS; t++) {
            float v = r0 * wv[0][t] + r1 * wv[1][t] + r2 * wv[2][t] + r3 * wv[3][t];
            g_weff[(((size_t)b * TAPS + t) * COUT + o) * CIN + c] = __float2half_rn(v);
        }
    }
}

// ---------------- kernel 4: batched implicit-GEMM conv via mma.sync (HMMA) ----------------
// CTA: b = blockIdx.z, mt = blockIdx.y (128 couts), nt = blockIdx.x (128 pixels = 4 rows)
// 128 threads = 4 warps, warp tile 64(m) x 64(n).
// 36 stages (cc-chunk major, tap minor). A quad-buffered, ONE barrier per stage PAIR.
// sX fill uses register transpose -> 8B packed shared stores.
constexpr int PIXB = 144;                 // bytes per pixel in sX (64 cin + 8 pad halves)
constexpr int ROWB = 34 * PIXB;           // 4896 B per image row (halo cols 0 and 33)
constexpr int SA_OFF   = 30720;           // >= 6*ROWB = 29376
constexpr int SA_BYTES = 128 * 128;       // 16 KB per A buffer
constexpr int CONV_SMEM = SA_OFF + 4 * SA_BYTES;   // 96256

__global__ __launch_bounds__(128, 2) void conv_kernel(float* __restrict__ out) {
    extern __shared__ char smem[];
    char* sx = smem;
    const uint32_t sxa = smem_u32(sx);

    const int tid = threadIdx.x, lid = tid & 31, wid = tid >> 5;
    const int nt = blockIdx.x, mt = blockIdx.y, b = blockIdx.z;
    const int wm = wid & 1, wn = wid >> 1;
    const int h0 = nt * 4;

    const __half* __restrict__ xb = g_xh + (size_t)b * CIN * HW;
    const __half* __restrict__ wbase =
        g_weff + ((size_t)b * TAPS * COUT + (size_t)mt * 128) * CIN;

    float acc[4][8][4];
    #pragma unroll
    for (int mi = 0; mi < 4; mi++)
        #pragma unroll
        for (int ni = 0; ni < 8; ni++)
            #pragma unroll
            for (int q = 0; q < 4; q++) acc[mi][ni][q] = 0.f;

    // ---- per-thread ldmatrix row addresses for B fragments ----
    uint32_t bg[4];
    {
        int kh = (lid >> 3) & 1, nodd = lid >> 4, pr = lid & 7;
        #pragma unroll
        for (int g = 0; g < 4; g++) {
            int n = wn * 64 + (2 * g + nodd) * 8 + pr;
            int r = n >> 5, w = n & 31;
            bg[g] = sxa + (uint32_t)(((r + 1) * 34 + (w + 1)) * PIXB + kh * 16);
        }
    }

    // A prefetch: stage s -> buffer s&3
    auto prefetchA = [&](int s) {
        const int tap = s % TAPS, cc = s / TAPS;
        const __half* asrc = wbase + (size_t)tap * COUT * CIN + cc * 64;
        const uint32_t dst = sxa + SA_OFF + (uint32_t)(s & 3) * SA_BYTES;
        #pragma unroll
        for (int i = 0; i < 8; i++) {
            int idx = i * 128 + tid;
            int m = idx >> 3, j = idx & 7;
            cp_async16(dst + SW128((uint32_t)(m * 128 + j * 16)), asrc + m * CIN + j * 8);
        }
    };

    // sX chunk fill: register-transpose, 8B packed stores
    auto fillX = [&](int cc) {
        #pragma unroll
        for (int it = 0; it < 3; it++) {
            int idx = it * 128 + tid;          // 0..383
            int cg = idx & 15;                 // 4-cin group
            int pg = (idx >> 4) & 3;           // 8-pixel group
            int rr = idx >> 6;                 // 0..5
            int h = h0 + rr - 1;
            uint4 v[4];
            if ((unsigned)h < 32u) {
                const __half* src = xb + (size_t)(cc * 64 + cg * 4) * HW + h * 32 + pg * 8;
                v[0] = *reinterpret_cast<const uint4*>(src);
                v[1] = *reinterpret_cast<const uint4*>(src + HW);
                v[2] = *reinterpret_cast<const uint4*>(src + 2 * HW);
                v[3] = *reinterpret_cast<const uint4*>(src + 3 * HW);
            } else {
                v[0] = v[1] = v[2] = v[3] = make_uint4(0u, 0u, 0u, 0u);
            }
            const ushort* u0 = reinterpret_cast<const ushort*>(&v[0]);
            const ushort* u1 = reinterpret_cast<const ushort*>(&v[1]);
            const ushort* u2 = reinterpret_cast<const ushort*>(&v[2]);
            const ushort* u3 = reinterpret_cast<const ushort*>(&v[3]);
            char* base = sx + rr * ROWB + (1 + pg * 8) * PIXB + cg * 8;
            #pragma unroll
            for (int p = 0; p < 8; p++) {
                uint2 w;
                w.x = (uint32_t)u0[p] | ((uint32_t)u1[p] << 16);
                w.y = (uint32_t)u2[p] | ((uint32_t)u3[p] << 16);
                *reinterpret_cast<uint2*>(base + p * PIXB) = w;
            }
        }
    };

    // compute one K=64 stage
    auto computeS = [&](int s) {
        const int tap = s % TAPS;
        const uint32_t sa = sxa + SA_OFF + (uint32_t)(s & 3) * SA_BYTES;
        const int dh = tap / 3 - 1, dw = tap % 3 - 1;
        const int delta = (dh * 34 + dw) * PIXB;
        #pragma unroll
        for (int ks = 0; ks < 4; ks++) {
            uint32_t afr[4][4];
            #pragma unroll
            for (int mi = 0; mi < 4; mi++) {
                int row = wm * 64 + mi * 16 + (lid & 15);
                uint32_t off = (uint32_t)(row * 128 + ks * 32 + (lid >> 4) * 16);
                ldsm_x4(afr[mi], sa + SW128(off));
            }
            uint32_t breg[4][4];
            const uint32_t dlt = (uint32_t)(delta + ks * 32);
            #pragma unroll
            for (int g = 0; g < 4; g++) ldsm_x4(breg[g], bg[g] + dlt);
            #pragma unroll
            for (int mi = 0; mi < 4; mi++)
                #pragma unroll
                for (int nb = 0; nb < 8; nb++) {
                    uint32_t b0 = breg[nb >> 1][(nb & 1) * 2];
                    uint32_t b1 = breg[nb >> 1][(nb & 1) * 2 + 1];
                    mma16816(acc[mi][nb], afr[mi], b0, b1);
                }
        }
    };

    // ---- prologue: zero halo columns (once) + prefetch stage pair {0,1} ----
    if (tid < 96) {
        int rr = tid / 16, sub = tid % 16;
        int col = (sub >> 3) ? 33 : 0, kq = sub & 7;
        *reinterpret_cast<uint4*>(sx + rr * ROWB + col * PIXB + kq * 16) =
            make_uint4(0u, 0u, 0u, 0u);
    }
    prefetchA(0);
    prefetchA(1);
    CP_COMMIT();

    #pragma unroll 1
    for (int k = 0; k < 18; k++) {
        CP_WAIT(0);                // A(2k), A(2k+1) resident (thread-local)
        __syncthreads();           // block-wide visibility; pair k-1 readers done
        if (k < 17) {              // prefetch pair k+1 (buffers disjoint from pair k)
            prefetchA(2 * k + 2);
            prefetchA(2 * k + 3);
            CP_COMMIT();
        }
        #pragma unroll
        for (int j = 0; j < 2; j++) {
            const int s = 2 * k + j;
            if (s % TAPS == 0) {   // chunk boundary: refill sX (uniform branch)
                __syncthreads();   // prior chunk's readers done
                fillX(s / TAPS);
                __syncthreads();
            }
            computeS(s);
        }
    }

    // ---- epilogue: accum regs -> out ----
    #pragma unroll
    for (int mi = 0; mi < 4; mi++) {
        #pragma unroll
        for (int ni = 0; ni < 8; ni++) {
            int row = mt * 128 + wm * 64 + mi * 16 + (lid >> 2);
            int col = nt * 128 + wn * 64 + ni * 8 + (lid & 3) * 2;
            float* op0 = out + ((size_t)b * COUT + row) * HW + col;
            float* op1 = op0 + 8 * HW;   // row + 8
            *reinterpret_cast<float2*>(op0) = make_float2(acc[mi][ni][0], acc[mi][ni][1]);
            *reinterpret_cast<float2*>(op1) = make_float2(acc[mi][ni][2], acc[mi][ni][3]);
        }
    }
}

// ---------------- launcher ----------------
extern "C" void kernel_launch(void* const* d_in, const int* in_sizes, int n_in,
                              void* d_out, int out_size) {
    const float* x      = (const float*)d_in[0];
    const float* te     = (const float*)d_in[1];
    const float* weight = (const float*)d_in[2];
    const float* Wq = (const float*)d_in[3],  *bq = (const float*)d_in[4];
    const float* Wk = (const float*)d_in[5],  *bk = (const float*)d_in[6];
    const float* Wv = (const float*)d_in[7],  *bv = (const float*)d_in[8];
    const float* Wm1 = (const float*)d_in[9],  *bm1 = (const float*)d_in[10];
    const float* Wm2 = (const float*)d_in[11], *bm2 = (const float*)d_in[12];
    const float* Wc  = (const float*)d_in[13], *bc  = (const float*)d_in[14];
    float* out = (float*)d_out;

    cudaFuncSetAttribute(conv_kernel, cudaFuncAttributeMaxDynamicSharedMemorySize,
                         CONV_SMEM);

    pool_convert_kernel<<<(B_ * CIN) / 8, 256>>>(x);
    router_kernel<<<B_, HID>>>(te, Wq, bq, Wk, bk, Wv, bv, Wm1, bm1, Wm2, bm2, Wc, bc);
    mix_kernel<<<COUT, 256>>>(weight);
    conv_kernel<<<dim3(8, 2, B_), 128, CONV_SMEM>>>(out);
}